// round 2
// baseline (speedup 1.0000x reference)
#include <cuda_runtime.h>
#include <stdint.h>

// Shape (fixed by dataset):
//   fx, fy : float32 [B=16, C=128, D=3, N=4096], topk=4 -> k = 1024
// Output: concat(fx_sel, fy_sel), each [16,128,3,1024] float32.

#define B_ 16
#define C_ 128
#define D_ 3
#define N_ 4096
#define K_ 1024

#define BATCH_STRIDE  ((long long)C_ * D_ * N_)       // 1,572,864
#define C_STRIDE      (D_ * N_)                       // 12,288
#define HALF_OUT      ((long long)B_ * C_ * D_ * K_)  // 6,291,456

// Scratch (__device__ globals: allocation-free rule)
__device__ unsigned long long g_key[B_ * N_];
__device__ int                g_idx[B_ * K_];

// ---------------------------------------------------------------------------
// Kernel 1: per-(b,n) score in FP64 (rank fidelity), emitted as a sortable
// 64-bit key with (4095 - n) packed in the low 12 bits (truncated from the
// mantissa; monotone). Descending sort on keys == descending score with
// ties broken by ascending index (matches jax.lax.top_k).
// ---------------------------------------------------------------------------
__global__ __launch_bounds__(256)
void score_kernel(const float* __restrict__ fx, const float* __restrict__ fy,
                  unsigned long long* __restrict__ key)
{
    int n = blockIdx.x * blockDim.x + threadIdx.x;   // 0..4095
    int b = blockIdx.y;                               // 0..15

    const float* px = fx + (long long)b * BATCH_STRIDE + n;
    const float* py = fy + (long long)b * BATCH_STRIDE + n;

    double mx0 = 0, mx1 = 0, mx2 = 0;
    double my0 = 0, my1 = 0, my2 = 0;
    double m00 = 0, m01 = 0, m02 = 0;
    double m10 = 0, m11 = 0, m12 = 0;
    double m20 = 0, m21 = 0, m22 = 0;

#pragma unroll 4
    for (int c = 0; c < C_; c++) {
        const float* rx = px + c * C_STRIDE;
        const float* ry = py + c * C_STRIDE;
        double x0 = (double)rx[0];
        double x1 = (double)rx[N_];
        double x2 = (double)rx[2 * N_];
        double y0 = (double)ry[0];
        double y1 = (double)ry[N_];
        double y2 = (double)ry[2 * N_];

        mx0 += x0; mx1 += x1; mx2 += x2;
        my0 += y0; my1 += y1; my2 += y2;

        m00 = fma(x0, y0, m00); m01 = fma(x0, y1, m01); m02 = fma(x0, y2, m02);
        m10 = fma(x1, y0, m10); m11 = fma(x1, y1, m11); m12 = fma(x1, y2, m12);
        m20 = fma(x2, y0, m20); m21 = fma(x2, y1, m21); m22 = fma(x2, y2, m22);
    }

    const double inv = 1.0 / (double)C_;
    mx0 *= inv; mx1 *= inv; mx2 *= inv;
    my0 *= inv; my1 *= inv; my2 *= inv;

    double nx = sqrt(mx0 * mx0 + mx1 * mx1 + mx2 * mx2) + 1e-6;
    double ny = sqrt(my0 * my0 + my1 * my1 + my2 * my2) + 1e-6;

    double fyp0 = my0 / ny, fyp1 = my1 / ny, fyp2 = my2 / ny;

    double v0 = m00 * fyp0 + m01 * fyp1 + m02 * fyp2;
    double v1 = m10 * fyp0 + m11 * fyp1 + m12 * fyp2;
    double v2 = m20 * fyp0 + m21 * fyp1 + m22 * fyp2;

    double s = (mx0 * v0 + mx1 * v1 + mx2 * v2) / nx;

    // Monotone double -> uint64 map
    unsigned long long u = __double_as_longlong(s);
    if (u & 0x8000000000000000ULL) u = ~u;
    else                           u |= 0x8000000000000000ULL;

    // Truncate 12 low mantissa bits (2^-40 relative; monotone non-strict),
    // pack (4095 - n): smaller index wins ties in descending sort.
    key[b * N_ + n] = (u & ~0xFFFULL) | (unsigned long long)(N_ - 1 - n);
}

// ---------------------------------------------------------------------------
// Kernel 2: per-batch full bitonic sort of 4096 u64 keys in smem (32 KB),
// emit top 1024 indices in rank order.
// ---------------------------------------------------------------------------
__global__ __launch_bounds__(1024)
void topk_kernel(const unsigned long long* __restrict__ key,
                 int* __restrict__ idxout)
{
    __shared__ unsigned long long keys[N_];
    int b = blockIdx.x;
    int tid = threadIdx.x;

    keys[tid]        = key[b * N_ + tid];
    keys[tid + 1024] = key[b * N_ + tid + 1024];
    keys[tid + 2048] = key[b * N_ + tid + 2048];
    keys[tid + 3072] = key[b * N_ + tid + 3072];
    __syncthreads();

    for (int k = 2; k <= N_; k <<= 1) {
        for (int j = k >> 1; j > 0; j >>= 1) {
#pragma unroll
            for (int it = 0; it < 4; it++) {
                int t = tid + it * 1024;
                int ixj = t ^ j;
                if (ixj > t) {
                    unsigned long long a = keys[t];
                    unsigned long long c = keys[ixj];
                    bool desc = ((t & k) == 0);
                    if (desc ? (a < c) : (a > c)) {
                        keys[t] = c;
                        keys[ixj] = a;
                    }
                }
            }
            __syncthreads();
        }
    }

    // keys[0..1023] = top-1024 descending
    idxout[b * K_ + tid] = (N_ - 1) - (int)(keys[tid] & 0xFFFULL);
}

// ---------------------------------------------------------------------------
// Kernel 3: gather selected columns. One thread per output element.
// Writes coalesced over j; reads are 4B gathers within 16 KB rows.
// ---------------------------------------------------------------------------
__global__ __launch_bounds__(256)
void gather_kernel(const float* __restrict__ fx, const float* __restrict__ fy,
                   const int* __restrict__ idx, float* __restrict__ out)
{
    long long t = (long long)blockIdx.x * blockDim.x + threadIdx.x;
    if (t >= 2 * HALF_OUT) return;

    const float* src = fx;
    float* dst = out;
    long long tt = t;
    if (tt >= HALF_OUT) {
        tt -= HALF_OUT;
        src = fy;
        dst = out + HALF_OUT;
    }

    int j = (int)(tt & (K_ - 1));
    long long rest = tt >> 10;          // (b*C + c)*D + d
    int d = (int)(rest % D_);
    long long bc = rest / D_;           // b*C + c
    int b = (int)(bc >> 7);

    int n = idx[b * K_ + j];

    dst[tt] = src[bc * (long long)C_STRIDE + (long long)d * N_ + n];
}

// ---------------------------------------------------------------------------
extern "C" void kernel_launch(void* const* d_in, const int* in_sizes, int n_in,
                              void* d_out, int out_size)
{
    const float* fx = (const float*)d_in[0];
    const float* fy = (const float*)d_in[1];
    float* out = (float*)d_out;

    unsigned long long* key;
    int* idx;
    cudaGetSymbolAddress((void**)&key, g_key);
    cudaGetSymbolAddress((void**)&idx, g_idx);

    dim3 g1(N_ / 256, B_);
    score_kernel<<<g1, 256>>>(fx, fy, key);

    topk_kernel<<<B_, 1024>>>(key, idx);

    long long total = 2 * HALF_OUT;
    int blocks = (int)((total + 255) / 256);
    gather_kernel<<<blocks, 256>>>(fx, fy, idx, out);
}